// round 5
// baseline (speedup 1.0000x reference)
#include <cuda_runtime.h>

#define Bn 64
#define Nn 512
#define Kk 32
#define Dd 64
#define BN_TOTAL (Bn*Nn)   // 32768
#define EPSf 1e-5f
#define NEG_SLOPE 0.2f
#define NEG_INFf -1e9f

// ---- scratch (static device globals; no allocation) ----
__device__ int   g_topk[Nn * Kk];
__device__ float g_xl[(size_t)BN_TOTAL * Dd];   // 8 MB
__device__ float g_ci[BN_TOTAL];
__device__ float g_cj[BN_TOTAL];

// ---- f32x2 packed helpers ----
__device__ __forceinline__ unsigned long long fma2(unsigned long long a,
                                                   unsigned long long b,
                                                   unsigned long long c) {
    unsigned long long d;
    asm("fma.rn.f32x2 %0, %1, %2, %3;" : "=l"(d) : "l"(a), "l"(b), "l"(c));
    return d;
}
__device__ __forceinline__ unsigned long long dup2(float x) {
    unsigned long long d; unsigned int u = __float_as_uint(x);
    asm("mov.b64 %0, {%1, %2};" : "=l"(d) : "r"(u), "r"(u));
    return d;
}
__device__ __forceinline__ float2 unpack2(unsigned long long v) {
    unsigned int lo, hi;
    asm("mov.b64 {%0, %1}, %2;" : "=r"(lo), "=r"(hi) : "l"(v));
    return make_float2(__uint_as_float(lo), __uint_as_float(hi));
}

// ---------------------------------------------------------------
// Kernel 1 (FUSED): cosine top-K directly from emb.
// 128 blocks x 128 threads; warp per target row (4 rows/block).
// Loop over 8 chunks of 64 source rows staged TRANSPOSED in smem;
// lane computes dot AND squared-norm of its 2 columns in one pass.
// Then 32 register-resident shuffle-argmax rounds.
// Tie-break: smaller index wins (matches jax.lax.top_k).
// ---------------------------------------------------------------
__global__ void __launch_bounds__(128)
k_costopk(const float* __restrict__ emb) {
    __shared__ float s_A[4][Dd];       // the 4 target rows
    __shared__ float s_B[Dd][66];      // chunk: s_B[k][j_local], padded

    const int tid = threadIdx.x;
    const int w = tid >> 5, t = tid & 31;
    const int i = blockIdx.x * 4 + w;
    const float4* emb4 = (const float4*)emb;

    if (tid < 64) {                    // stage 4 target rows (coalesced)
        int r = tid >> 4, q = tid & 15;
        ((float4*)s_A[r])[q] = emb4[(blockIdx.x * 4 + r) * 16 + q];
    }
    __syncthreads();

    // own-row inverse norm
    float a0 = s_A[w][2 * t], a1 = s_A[w][2 * t + 1];
    float ni = a0 * a0 + a1 * a1;
#pragma unroll
    for (int o = 16; o > 0; o >>= 1) ni += __shfl_xor_sync(0xFFFFFFFFu, ni, o);
    const float inv_i = rsqrtf(ni);

    unsigned long long key[16];

#pragma unroll 1
    for (int c = 0; c < 8; c++) {
        __syncthreads();
        // stage chunk rows c*64..c*64+63 transposed: s_B[k][r]
        for (int it = tid; it < 1024; it += 128) {
            int r = it >> 4, q = it & 15;
            float4 v = emb4[(c * 64 + r) * 16 + q];
            s_B[4 * q + 0][r] = v.x;
            s_B[4 * q + 1][r] = v.y;
            s_B[4 * q + 2][r] = v.z;
            s_B[4 * q + 3][r] = v.w;
        }
        __syncthreads();

        float d0 = 0.f, d1 = 0.f, n0 = 0.f, n1 = 0.f;
#pragma unroll
        for (int k = 0; k < Dd; k++) {
            const float a = s_A[w][k];                       // broadcast
            const float2 b = *(const float2*)&s_B[k][2 * t]; // conflict-free LDS.64
            d0 = fmaf(a, b.x, d0);
            n0 = fmaf(b.x, b.x, n0);
            d1 = fmaf(a, b.y, d1);
            n1 = fmaf(b.y, b.y, n1);
        }
        const int j0 = c * 64 + 2 * t;
        const float cos0 = d0 * inv_i * rsqrtf(n0);
        const float cos1 = d1 * inv_i * rsqrtf(n1);
        unsigned int b0 = __float_as_uint(cos0);
        b0 = (b0 & 0x80000000u) ? ~b0 : (b0 | 0x80000000u);
        unsigned int b1 = __float_as_uint(cos1);
        b1 = (b1 & 0x80000000u) ? ~b1 : (b1 | 0x80000000u);
        key[2 * c]     = ((unsigned long long)b0 << 32) | (unsigned int)(Nn - 1 - j0);
        key[2 * c + 1] = ((unsigned long long)b1 << 32) | (unsigned int)(Nn - 2 - j0);
    }

    // 32 shuffle-argmax rounds
    for (int k = 0; k < Kk; k++) {
        unsigned long long best = 0ull;
#pragma unroll
        for (int m = 0; m < 16; m++) best = (key[m] > best) ? key[m] : best;
#pragma unroll
        for (int o = 16; o > 0; o >>= 1) {
            unsigned long long v = __shfl_xor_sync(0xFFFFFFFFu, best, o);
            best = (v > best) ? v : best;
        }
#pragma unroll
        for (int m = 0; m < 16; m++) if (key[m] == best) key[m] = 0ull;
        if (t == 0) g_topk[i * Kk + k] = Nn - 1 - (int)(best & 0xFFFFFFFFu);
    }
}

// ---------------------------------------------------------------
// Kernel 2: xl = x @ W^T, per-node scalars ci/cj, edot folded in.
// ---------------------------------------------------------------
#define XT_STRIDE 66
__global__ void __launch_bounds__(256)
k_xl(const float* __restrict__ x,
     const float* __restrict__ W,
     const float* __restrict__ emb,
     const float* __restrict__ att_i,
     const float* __restrict__ att_j,
     const float* __restrict__ att_em_i,
     const float* __restrict__ att_em_j) {
    __shared__ float s_W[Dd][Dd + 1];        // s_W[k][d] = W[d][k]
    __shared__ float s_xt[Dd][XT_STRIDE];    // s_xt[k][n_local]
    __shared__ float s_edi[64], s_edj[64];

    const int tid = threadIdx.x;
    const int w = tid >> 5, t = tid & 31;
    const int node_blk = blockIdx.x * 64;
    const int l0 = node_blk & (Nn - 1);      // 64-aligned local base

    for (int idx = tid; idx < Dd * Dd; idx += 256) {
        int d = idx >> 6, k = idx & 63;
        s_W[k][d] = W[idx];
    }
    {
        const float4* xs = (const float4*)(x + (size_t)node_blk * Dd);
#pragma unroll
        for (int v = tid; v < 1024; v += 256) {
            float4 val = xs[v];
            int n = v >> 4, q = (v & 15) * 4;
            float* dst = &s_xt[0][0] + q * XT_STRIDE + n;
            dst[0]             = val.x;
            dst[XT_STRIDE]     = val.y;
            dst[2 * XT_STRIDE] = val.z;
            dst[3 * XT_STRIDE] = val.w;
        }
    }
    __syncthreads();

    const float ai0 = att_i[t], ai1 = att_i[t + 32];
    const float aj0 = att_j[t], aj1 = att_j[t + 32];

    unsigned long long accA[4] = {0ull, 0ull, 0ull, 0ull};
    unsigned long long accB[4] = {0ull, 0ull, 0ull, 0ull};
    const int nl0 = w * 8;

#pragma unroll 16
    for (int k = 0; k < Dd; k++) {
        const unsigned long long wd0 = dup2(s_W[k][t]);
        const unsigned long long wd1 = dup2(s_W[k][t + 32]);
        const unsigned long long* xrow =
            (const unsigned long long*)(&s_xt[0][0] + k * XT_STRIDE + nl0);
#pragma unroll
        for (int p = 0; p < 4; p++) {
            const unsigned long long xp = xrow[p];
            accA[p] = fma2(xp, wd0, accA[p]);
            accB[p] = fma2(xp, wd1, accB[p]);
        }
    }

    // edot for the 64 locals of this block (2 warps, tail work)
    if (tid < 64) {
        const float* er = emb + (size_t)(l0 + tid) * Dd;
        float di = 0.f, dj = 0.f;
#pragma unroll 8
        for (int d = 0; d < Dd; d++) {
            float e = __ldg(er + d);
            di = fmaf(e, __ldg(att_em_i + d), di);
            dj = fmaf(e, __ldg(att_em_j + d), dj);
        }
        s_edi[tid] = di;
        s_edj[tid] = dj;
    }
    __syncthreads();

#pragma unroll
    for (int p = 0; p < 4; p++) {
        const float2 a = unpack2(accA[p]);
        const float2 b = unpack2(accB[p]);
        const int n0 = node_blk + nl0 + 2 * p;
        const int n1 = n0 + 1;
        g_xl[(size_t)n0 * Dd + t]      = a.x;
        g_xl[(size_t)n0 * Dd + t + 32] = b.x;
        g_xl[(size_t)n1 * Dd + t]      = a.y;
        g_xl[(size_t)n1 * Dd + t + 32] = b.y;

        float pi0 = a.x * ai0 + b.x * ai1, pj0 = a.x * aj0 + b.x * aj1;
        float pi1 = a.y * ai0 + b.y * ai1, pj1 = a.y * aj0 + b.y * aj1;
#pragma unroll
        for (int o = 16; o > 0; o >>= 1) {
            pi0 += __shfl_xor_sync(0xFFFFFFFFu, pi0, o);
            pj0 += __shfl_xor_sync(0xFFFFFFFFu, pj0, o);
            pi1 += __shfl_xor_sync(0xFFFFFFFFu, pi1, o);
            pj1 += __shfl_xor_sync(0xFFFFFFFFu, pj1, o);
        }
        if (t == 0) {
            const int ll0 = nl0 + 2 * p, ll1 = ll0 + 1;
            g_ci[n0] = pi0 + s_edi[ll0];
            g_cj[n0] = pj0 + s_edj[ll0];
            g_ci[n1] = pi1 + s_edi[ll1];
            g_cj[n1] = pj1 + s_edj[ll1];
        }
    }
}

// ---------------------------------------------------------------
// Kernel 3: attention + epilogue.
// 4096 blocks x 256 threads, warp per target (round-1 shape),
// staged s_cj, LDG.64 gather, folded BN constants.
// Consecutive blocks share a batch -> L2 locality on xl slice.
// ---------------------------------------------------------------
__global__ void __launch_bounds__(256)
k_attn(const float* __restrict__ emb,
       const float* __restrict__ gnn_bias,
       const float* __restrict__ bn1_gamma, const float* __restrict__ bn1_beta,
       const float* __restrict__ bn1_mean,  const float* __restrict__ bn1_var,
       const float* __restrict__ bno_gamma, const float* __restrict__ bno_beta,
       const float* __restrict__ bno_mean,  const float* __restrict__ bno_var,
       const float* __restrict__ out_W,     const float* __restrict__ out_b,
       float* __restrict__ out) {
    __shared__ float  s_cj[Nn];
    __shared__ float2 s_ws[8][32];

    const int tid = threadIdx.x;
    const int w = tid >> 5, t = tid & 31;
    const int batch = blockIdx.x >> 6;                 // 64 blocks per batch
    const int li = (blockIdx.x & 63) * 8 + w;          // local target
    const int base = batch * Nn;
    const int node = base + li;

    {   // stage cj for this batch (coalesced float2)
        float2 v = *(const float2*)(g_cj + base + 2 * tid);
        *(float2*)&s_cj[2 * tid] = v;
    }
    __syncthreads();

    // folded per-lane constants for channel pair (2t, 2t+1)
    const float2 gb = ((const float2*)gnn_bias)[t];
    const float2 g1 = ((const float2*)bn1_gamma)[t];
    const float2 b1 = ((const float2*)bn1_beta)[t];
    const float2 m1 = ((const float2*)bn1_mean)[t];
    const float2 v1 = ((const float2*)bn1_var)[t];
    const float2 go = ((const float2*)bno_gamma)[t];
    const float2 bo = ((const float2*)bno_beta)[t];
    const float2 mo = ((const float2*)bno_mean)[t];
    const float2 vo = ((const float2*)bno_var)[t];
    const float2 ow = ((const float2*)out_W)[t];
    const float  ob = out_b[0];
    const float s1x = rsqrtf(v1.x + EPSf) * g1.x;
    const float s1y = rsqrtf(v1.y + EPSf) * g1.y;
    const float C1x = (gb.x - m1.x) * s1x + b1.x;
    const float C1y = (gb.y - m1.y) * s1y + b1.y;
    const float sox = rsqrtf(vo.x + EPSf) * go.x;
    const float soy = rsqrtf(vo.y + EPSf) * go.y;
    const float Cox = bo.x - mo.x * sox;
    const float Coy = bo.y - mo.y * soy;

    const float ci = g_ci[node];
    const int srcj = g_topk[li * Kk + t];
    const bool valid = (srcj != li);

    float lg = ci + s_cj[srcj];
    lg = (lg >= 0.f) ? lg : NEG_SLOPE * lg;
    if (!valid) lg = NEG_INFf;

    float lgs = ci + s_cj[li];
    lgs = (lgs >= 0.f) ? lgs : NEG_SLOPE * lgs;

    float m = lg;
#pragma unroll
    for (int o = 16; o > 0; o >>= 1) m = fmaxf(m, __shfl_xor_sync(0xFFFFFFFFu, m, o));
    m = fmaxf(m, lgs);

    const float ex  = valid ? __expf(lg - m) : 0.0f;
    const float exs = __expf(lgs - m);
    float sum = ex;
#pragma unroll
    for (int o = 16; o > 0; o >>= 1) sum += __shfl_xor_sync(0xFFFFFFFFu, sum, o);
    const float inv = 1.0f / (sum + exs);              // warp-uniform

    s_ws[w][t] = make_float2(ex * inv, __int_as_float(srcj));
    __syncwarp();

    const float* xb = g_xl + (size_t)base * Dd;
    const float wself = exs * inv;
    const float2 vs = *(const float2*)(xb + li * Dd + 2 * t);
    float acc0 = wself * vs.x, acc1 = wself * vs.y;

#pragma unroll 8
    for (int e = 0; e < Kk; e++) {
        const float2 ws = s_ws[w][e];                  // 8B broadcast LDS
        const int se = __float_as_int(ws.y);
        const float2 v = *(const float2*)(xb + se * Dd + 2 * t);   // LDG.64
        acc0 = fmaf(ws.x, v.x, acc0);
        acc1 = fmaf(ws.x, v.y, acc1);
    }

    // epilogue
    const float2 em = *(const float2*)(emb + li * Dd + 2 * t);
    float h0 = fmaxf(fmaf(acc0, s1x, C1x), 0.f) * em.x;
    float h1 = fmaxf(fmaf(acc1, s1y, C1y), 0.f) * em.y;
    h0 = fmaxf(fmaf(h0, sox, Cox), 0.f);
    h1 = fmaxf(fmaf(h1, soy, Coy), 0.f);

    float p = h0 * ow.x + h1 * ow.y;
#pragma unroll
    for (int o = 16; o > 0; o >>= 1) p += __shfl_xor_sync(0xFFFFFFFFu, p, o);
    if (t == 0) out[node] = p + ob;
}

// ---------------------------------------------------------------
extern "C" void kernel_launch(void* const* d_in, const int* in_sizes, int n_in,
                              void* d_out, int out_size) {
    (void)in_sizes; (void)n_in; (void)out_size;
    const float* data      = (const float*)d_in[0];
    /* d_in[1] = org_edge_index — unused by the model */
    const float* emb       = (const float*)d_in[2];
    const float* lin_W     = (const float*)d_in[3];
    const float* att_i     = (const float*)d_in[4];
    const float* att_j     = (const float*)d_in[5];
    const float* att_em_i  = (const float*)d_in[6];
    const float* att_em_j  = (const float*)d_in[7];
    const float* gnn_bias  = (const float*)d_in[8];
    const float* bn1_gamma = (const float*)d_in[9];
    const float* bn1_beta  = (const float*)d_in[10];
    const float* bn1_mean  = (const float*)d_in[11];
    const float* bn1_var   = (const float*)d_in[12];
    const float* bno_gamma = (const float*)d_in[13];
    const float* bno_beta  = (const float*)d_in[14];
    const float* bno_mean  = (const float*)d_in[15];
    const float* bno_var   = (const float*)d_in[16];
    const float* out_W     = (const float*)d_in[17];
    const float* out_b     = (const float*)d_in[18];
    float* out = (float*)d_out;

    k_costopk<<<Nn / 4, 128>>>(emb);
    k_xl<<<BN_TOTAL / 64, 256>>>(data, lin_W, emb, att_i, att_j, att_em_i, att_em_j);
    k_attn<<<BN_TOTAL / 8, 256>>>(emb, gnn_bias,
                                  bn1_gamma, bn1_beta, bn1_mean, bn1_var,
                                  bno_gamma, bno_beta, bno_mean, bno_var,
                                  out_W, out_b, out);
}

// round 6
// speedup vs baseline: 1.1504x; 1.1504x over previous
#include <cuda_runtime.h>

#define Bn 64
#define Nn 512
#define Kk 32
#define Dd 64
#define BN_TOTAL (Bn*Nn)   // 32768
#define EPSf 1e-5f
#define NEG_SLOPE 0.2f
#define NEG_INFf -1e9f

// ---- scratch (static device globals; no allocation) ----
__device__ float g_invn[Nn];
__device__ float g_edot_i[Nn];
__device__ float g_edot_j[Nn];
__device__ float g_cos[Nn * Nn];                // 1 MB
__device__ int   g_topk[Nn * Kk];
__device__ float g_xl[(size_t)BN_TOTAL * Dd];   // 8 MB
__device__ float g_ci[BN_TOTAL];
__device__ float g_cj[BN_TOTAL];

// ---- f32x2 packed helpers ----
__device__ __forceinline__ unsigned long long fma2(unsigned long long a,
                                                   unsigned long long b,
                                                   unsigned long long c) {
    unsigned long long d;
    asm("fma.rn.f32x2 %0, %1, %2, %3;" : "=l"(d) : "l"(a), "l"(b), "l"(c));
    return d;
}
__device__ __forceinline__ unsigned long long dup2(float x) {
    unsigned long long d; unsigned int u = __float_as_uint(x);
    asm("mov.b64 %0, {%1, %2};" : "=l"(d) : "r"(u), "r"(u));
    return d;
}
__device__ __forceinline__ float2 unpack2(unsigned long long v) {
    unsigned int lo, hi;
    asm("mov.b64 {%0, %1}, %2;" : "=r"(lo), "=r"(hi) : "l"(v));
    return make_float2(__uint_as_float(lo), __uint_as_float(hi));
}
__device__ __forceinline__ unsigned long long umax64(unsigned long long a,
                                                     unsigned long long b) {
    return a > b ? a : b;
}
__device__ __forceinline__ unsigned long long umin64(unsigned long long a,
                                                     unsigned long long b) {
    return a < b ? a : b;
}

// ---------------------------------------------------------------
// Kernel 1: inverse norm + dot products with att_em_{i,j}
// ---------------------------------------------------------------
__global__ void k_norms(const float* __restrict__ emb,
                        const float* __restrict__ att_em_i,
                        const float* __restrict__ att_em_j) {
    int n = blockIdx.x * blockDim.x + threadIdx.x;
    if (n >= Nn) return;
    const float* row = emb + n * Dd;
    float s2 = 0.f, di = 0.f, dj = 0.f;
#pragma unroll 8
    for (int d = 0; d < Dd; d++) {
        float e = row[d];
        s2 += e * e;
        di += e * att_em_i[d];
        dj += e * att_em_j[d];
    }
    g_invn[n]   = rsqrtf(s2);
    g_edot_i[n] = di;
    g_edot_j[n] = dj;
}

// ---------------------------------------------------------------
// Kernel 2: cos = diag(1/n) (E E^T) diag(1/n), tiled GEMM.
// ---------------------------------------------------------------
__global__ void __launch_bounds__(256)
k_cos(const float* __restrict__ emb) {
    __shared__ float s_A[32][65];
    __shared__ float s_B[64][65];

    const int tid = threadIdx.x;
    const int w = tid >> 5, t = tid & 31;
    const int i0 = blockIdx.y * 32;
    const int j0 = blockIdx.x * 64;

    for (int idx = tid; idx < 32 * 32; idx += 256) {
        int r = idx >> 5, c = idx & 31;
        float2 v = ((const float2*)(emb + (i0 + r) * Dd))[c];
        s_A[r][2 * c] = v.x; s_A[r][2 * c + 1] = v.y;
    }
    for (int idx = tid; idx < 64 * 32; idx += 256) {
        int r = idx >> 5, c = idx & 31;
        float2 v = ((const float2*)(emb + (j0 + r) * Dd))[c];
        s_B[r][2 * c] = v.x; s_B[r][2 * c + 1] = v.y;
    }
    __syncthreads();

    float acc[4][2] = {};
#pragma unroll 8
    for (int k = 0; k < Dd; k++) {
        const float b0 = s_B[t][k];
        const float b1 = s_B[t + 32][k];
#pragma unroll
        for (int a = 0; a < 4; a++) {
            const float av = s_A[w * 4 + a][k];
            acc[a][0] += av * b0;
            acc[a][1] += av * b1;
        }
    }

    const float invj0 = g_invn[j0 + t];
    const float invj1 = g_invn[j0 + t + 32];
#pragma unroll
    for (int a = 0; a < 4; a++) {
        const int irow = i0 + w * 4 + a;
        const float inv_i = g_invn[irow];
        g_cos[irow * Nn + j0 + t]      = acc[a][0] * inv_i * invj0;
        g_cos[irow * Nn + j0 + t + 32] = acc[a][1] * inv_i * invj1;
    }
}

// ---------------------------------------------------------------
// Kernel 3: parallel bitonic top-K. One block (8 warps) per row.
// Warp w: top-32 of candidates [64w, 64w+64) via bitonic sort+merge;
// then 3 smem merge levels (halving lemma). No serial rounds.
// Tie-break: smaller index (encoded in key low bits).
// ---------------------------------------------------------------
__global__ void __launch_bounds__(256)
k_topk() {
    __shared__ unsigned long long s_k[14][32];   // [0..7] L1, [8..11] L2, [12..13] L3

    const int tid = threadIdx.x;
    const int w = tid >> 5, l = tid & 31;
    const int i = blockIdx.x;
    const float* crow = g_cos + i * Nn;

    // build keys for this warp's 64 candidates
    const int j0 = w * 64 + l;
    const int j1 = j0 + 32;
    unsigned int b0 = __float_as_uint(crow[j0]);
    b0 = (b0 & 0x80000000u) ? ~b0 : (b0 | 0x80000000u);
    unsigned int b1 = __float_as_uint(crow[j1]);
    b1 = (b1 & 0x80000000u) ? ~b1 : (b1 | 0x80000000u);
    unsigned long long v0 = ((unsigned long long)b0 << 32) | (unsigned int)(Nn - 1 - j0);
    unsigned long long v1 = ((unsigned long long)b1 << 32) | (unsigned int)(Nn - 1 - j1);

    // descending bitonic sort of each 32-list (both slots overlapped)
#pragma unroll
    for (int k = 2; k <= 32; k <<= 1) {
#pragma unroll
        for (int j = k >> 1; j > 0; j >>= 1) {
            const bool keepMax = (((l & j) == 0) == ((l & k) == 0));
            unsigned long long o0 = __shfl_xor_sync(0xFFFFFFFFu, v0, j);
            unsigned long long o1 = __shfl_xor_sync(0xFFFFFFFFu, v1, j);
            v0 = keepMax ? umax64(v0, o0) : umin64(v0, o0);
            v1 = keepMax ? umax64(v1, o1) : umin64(v1, o1);
        }
    }

    // top-32 of 64: elementwise max with reversed second list, then 5-step merge
    unsigned long long m = umax64(v0, __shfl_xor_sync(0xFFFFFFFFu, v1, 31));
#pragma unroll
    for (int j = 16; j > 0; j >>= 1) {
        unsigned long long o = __shfl_xor_sync(0xFFFFFFFFu, m, j);
        m = ((l & j) == 0) ? umax64(m, o) : umin64(m, o);
    }
    s_k[w][l] = m;
    __syncthreads();

    // level 2: 4 warps merge pairs (reversed smem read replaces shuffle)
    if (w < 4) {
        unsigned long long a = s_k[2 * w][l];
        unsigned long long b = s_k[2 * w + 1][31 - l];
        unsigned long long m2 = umax64(a, b);
#pragma unroll
        for (int j = 16; j > 0; j >>= 1) {
            unsigned long long o = __shfl_xor_sync(0xFFFFFFFFu, m2, j);
            m2 = ((l & j) == 0) ? umax64(m2, o) : umin64(m2, o);
        }
        s_k[8 + w][l] = m2;
    }
    __syncthreads();

    // level 3: 2 warps
    if (w < 2) {
        unsigned long long a = s_k[8 + 2 * w][l];
        unsigned long long b = s_k[8 + 2 * w + 1][31 - l];
        unsigned long long m3 = umax64(a, b);
#pragma unroll
        for (int j = 16; j > 0; j >>= 1) {
            unsigned long long o = __shfl_xor_sync(0xFFFFFFFFu, m3, j);
            m3 = ((l & j) == 0) ? umax64(m3, o) : umin64(m3, o);
        }
        s_k[12 + w][l] = m3;
    }
    __syncthreads();

    // level 4: warp 0; final set needs no re-sort (order-invariant downstream)
    if (w == 0) {
        unsigned long long a = s_k[12][l];
        unsigned long long b = s_k[13][31 - l];
        unsigned long long m4 = umax64(a, b);
        g_topk[i * Kk + l] = Nn - 1 - (int)(m4 & 0xFFFFFFFFu);
    }
}

// ---------------------------------------------------------------
// Kernel 4: xl = x @ W^T and per-node scalars ci, cj (f32x2 packed).
// ---------------------------------------------------------------
#define XT_STRIDE 66
__global__ void __launch_bounds__(256)
k_xl(const float* __restrict__ x,
     const float* __restrict__ W,
     const float* __restrict__ att_i,
     const float* __restrict__ att_j) {
    __shared__ float s_W[Dd][Dd + 1];        // s_W[k][d] = W[d][k]
    __shared__ float s_xt[Dd][XT_STRIDE];    // s_xt[k][n_local]

    const int tid = threadIdx.x;
    const int w = tid >> 5, t = tid & 31;
    const int node_blk = blockIdx.x * 64;

    for (int idx = tid; idx < Dd * Dd; idx += 256) {
        int d = idx >> 6, k = idx & 63;
        s_W[k][d] = W[idx];
    }
    {
        const float4* xs = (const float4*)(x + (size_t)node_blk * Dd);
#pragma unroll
        for (int v = tid; v < 1024; v += 256) {
            float4 val = xs[v];
            int n = v >> 4, q = (v & 15) * 4;
            float* dst = &s_xt[0][0] + q * XT_STRIDE + n;
            dst[0]             = val.x;
            dst[XT_STRIDE]     = val.y;
            dst[2 * XT_STRIDE] = val.z;
            dst[3 * XT_STRIDE] = val.w;
        }
    }
    __syncthreads();

    const float ai0 = att_i[t], ai1 = att_i[t + 32];
    const float aj0 = att_j[t], aj1 = att_j[t + 32];

    unsigned long long accA[4] = {0ull, 0ull, 0ull, 0ull};
    unsigned long long accB[4] = {0ull, 0ull, 0ull, 0ull};
    const int nl0 = w * 8;

#pragma unroll 16
    for (int k = 0; k < Dd; k++) {
        const unsigned long long wd0 = dup2(s_W[k][t]);
        const unsigned long long wd1 = dup2(s_W[k][t + 32]);
        const unsigned long long* xrow =
            (const unsigned long long*)(&s_xt[0][0] + k * XT_STRIDE + nl0);
#pragma unroll
        for (int p = 0; p < 4; p++) {
            const unsigned long long xp = xrow[p];
            accA[p] = fma2(xp, wd0, accA[p]);
            accB[p] = fma2(xp, wd1, accB[p]);
        }
    }

#pragma unroll
    for (int p = 0; p < 4; p++) {
        const float2 a = unpack2(accA[p]);
        const float2 b = unpack2(accB[p]);
        const int n0 = node_blk + nl0 + 2 * p;
        const int n1 = n0 + 1;
        g_xl[(size_t)n0 * Dd + t]      = a.x;
        g_xl[(size_t)n0 * Dd + t + 32] = b.x;
        g_xl[(size_t)n1 * Dd + t]      = a.y;
        g_xl[(size_t)n1 * Dd + t + 32] = b.y;

        float pi0 = a.x * ai0 + b.x * ai1, pj0 = a.x * aj0 + b.x * aj1;
        float pi1 = a.y * ai0 + b.y * ai1, pj1 = a.y * aj0 + b.y * aj1;
#pragma unroll
        for (int o = 16; o > 0; o >>= 1) {
            pi0 += __shfl_xor_sync(0xFFFFFFFFu, pi0, o);
            pj0 += __shfl_xor_sync(0xFFFFFFFFu, pj0, o);
            pi1 += __shfl_xor_sync(0xFFFFFFFFu, pi1, o);
            pj1 += __shfl_xor_sync(0xFFFFFFFFu, pj1, o);
        }
        if (t == 0) {
            const int l0 = n0 & (Nn - 1), l1 = n1 & (Nn - 1);
            g_ci[n0] = pi0 + g_edot_i[l0];
            g_cj[n0] = pj0 + g_edot_j[l0];
            g_ci[n1] = pi1 + g_edot_i[l1];
            g_cj[n1] = pj1 + g_edot_j[l1];
        }
    }
}

// ---------------------------------------------------------------
// Kernel 5: attention + epilogue. 4096 blocks x 256 threads,
// warp per target, staged s_cj, LDG.64 gather, folded BN constants.
// ---------------------------------------------------------------
__global__ void __launch_bounds__(256)
k_attn(const float* __restrict__ emb,
       const float* __restrict__ gnn_bias,
       const float* __restrict__ bn1_gamma, const float* __restrict__ bn1_beta,
       const float* __restrict__ bn1_mean,  const float* __restrict__ bn1_var,
       const float* __restrict__ bno_gamma, const float* __restrict__ bno_beta,
       const float* __restrict__ bno_mean,  const float* __restrict__ bno_var,
       const float* __restrict__ out_W,     const float* __restrict__ out_b,
       float* __restrict__ out) {
    __shared__ float  s_cj[Nn];
    __shared__ float2 s_ws[8][32];

    const int tid = threadIdx.x;
    const int w = tid >> 5, t = tid & 31;
    const int batch = blockIdx.x >> 6;                 // 64 blocks per batch
    const int li = (blockIdx.x & 63) * 8 + w;          // local target
    const int base = batch * Nn;
    const int node = base + li;

    {
        float2 v = *(const float2*)(g_cj + base + 2 * tid);
        *(float2*)&s_cj[2 * tid] = v;
    }
    __syncthreads();

    const float2 gb = ((const float2*)gnn_bias)[t];
    const float2 g1 = ((const float2*)bn1_gamma)[t];
    const float2 b1 = ((const float2*)bn1_beta)[t];
    const float2 m1 = ((const float2*)bn1_mean)[t];
    const float2 v1 = ((const float2*)bn1_var)[t];
    const float2 go = ((const float2*)bno_gamma)[t];
    const float2 bo = ((const float2*)bno_beta)[t];
    const float2 mo = ((const float2*)bno_mean)[t];
    const float2 vo = ((const float2*)bno_var)[t];
    const float2 ow = ((const float2*)out_W)[t];
    const float  ob = out_b[0];
    const float s1x = rsqrtf(v1.x + EPSf) * g1.x;
    const float s1y = rsqrtf(v1.y + EPSf) * g1.y;
    const float C1x = (gb.x - m1.x) * s1x + b1.x;
    const float C1y = (gb.y - m1.y) * s1y + b1.y;
    const float sox = rsqrtf(vo.x + EPSf) * go.x;
    const float soy = rsqrtf(vo.y + EPSf) * go.y;
    const float Cox = bo.x - mo.x * sox;
    const float Coy = bo.y - mo.y * soy;

    const float ci = g_ci[node];
    const int srcj = g_topk[li * Kk + t];
    const bool valid = (srcj != li);

    float lg = ci + s_cj[srcj];
    lg = (lg >= 0.f) ? lg : NEG_SLOPE * lg;
    if (!valid) lg = NEG_INFf;

    float lgs = ci + s_cj[li];
    lgs = (lgs >= 0.f) ? lgs : NEG_SLOPE * lgs;

    float m = lg;
#pragma unroll
    for (int o = 16; o > 0; o >>= 1) m = fmaxf(m, __shfl_xor_sync(0xFFFFFFFFu, m, o));
    m = fmaxf(m, lgs);

    const float ex  = valid ? __expf(lg - m) : 0.0f;
    const float exs = __expf(lgs - m);
    float sum = ex;
#pragma unroll
    for (int o = 16; o > 0; o >>= 1) sum += __shfl_xor_sync(0xFFFFFFFFu, sum, o);
    const float inv = 1.0f / (sum + exs);

    s_ws[w][t] = make_float2(ex * inv, __int_as_float(srcj));
    __syncwarp();

    const float* xb = g_xl + (size_t)base * Dd;
    const float wself = exs * inv;
    const float2 vs = *(const float2*)(xb + li * Dd + 2 * t);
    float acc0 = wself * vs.x, acc1 = wself * vs.y;

#pragma unroll 8
    for (int e = 0; e < Kk; e++) {
        const float2 ws = s_ws[w][e];
        const int se = __float_as_int(ws.y);
        const float2 v = *(const float2*)(xb + se * Dd + 2 * t);
        acc0 = fmaf(ws.x, v.x, acc0);
        acc1 = fmaf(ws.x, v.y, acc1);
    }

    const float2 em = *(const float2*)(emb + li * Dd + 2 * t);
    float h0 = fmaxf(fmaf(acc0, s1x, C1x), 0.f) * em.x;
    float h1 = fmaxf(fmaf(acc1, s1y, C1y), 0.f) * em.y;
    h0 = fmaxf(fmaf(h0, sox, Cox), 0.f);
    h1 = fmaxf(fmaf(h1, soy, Coy), 0.f);

    float p = h0 * ow.x + h1 * ow.y;
#pragma unroll
    for (int o = 16; o > 0; o >>= 1) p += __shfl_xor_sync(0xFFFFFFFFu, p, o);
    if (t == 0) out[node] = p + ob;
}

// ---------------------------------------------------------------
extern "C" void kernel_launch(void* const* d_in, const int* in_sizes, int n_in,
                              void* d_out, int out_size) {
    (void)in_sizes; (void)n_in; (void)out_size;
    const float* data      = (const float*)d_in[0];
    /* d_in[1] = org_edge_index — unused by the model */
    const float* emb       = (const float*)d_in[2];
    const float* lin_W     = (const float*)d_in[3];
    const float* att_i     = (const float*)d_in[4];
    const float* att_j     = (const float*)d_in[5];
    const float* att_em_i  = (const float*)d_in[6];
    const float* att_em_j  = (const float*)d_in[7];
    const float* gnn_bias  = (const float*)d_in[8];
    const float* bn1_gamma = (const float*)d_in[9];
    const float* bn1_beta  = (const float*)d_in[10];
    const float* bn1_mean  = (const float*)d_in[11];
    const float* bn1_var   = (const float*)d_in[12];
    const float* bno_gamma = (const float*)d_in[13];
    const float* bno_beta  = (const float*)d_in[14];
    const float* bno_mean  = (const float*)d_in[15];
    const float* bno_var   = (const float*)d_in[16];
    const float* out_W     = (const float*)d_in[17];
    const float* out_b     = (const float*)d_in[18];
    float* out = (float*)d_out;

    k_norms<<<2, 256>>>(emb, att_em_i, att_em_j);
    k_cos<<<dim3(Nn / 64, Nn / 32), 256>>>(emb);
    k_xl<<<BN_TOTAL / 64, 256>>>(data, lin_W, att_i, att_j);
    k_topk<<<Nn, 256>>>();
    k_attn<<<BN_TOTAL / 8, 256>>>(emb, gnn_bias,
                                  bn1_gamma, bn1_beta, bn1_mean, bn1_var,
                                  bno_gamma, bno_beta, bno_mean, bno_var,
                                  out_W, out_b, out);
}